// round 3
// baseline (speedup 1.0000x reference)
#include <cuda_runtime.h>
#include <math.h>

#define NN 50000
#define EE 1600000
#define HID 64
#define NC 32
#define NFEAT 128
#define KG 16          // k-groups (64/4)
#define GW 128         // group width = 4*32 floats
#define CSTF 1e-5f
#define FULL 0xffffffffu

// ---------------- scratch (device globals; no allocation allowed) ----------
__device__ int   g_deg[NN];
__device__ float g_dinv[NN];
__device__ int   g_cptr[NN + 1];
__device__ int   g_cnt[NN];
__device__ int   g_src[EE];
__device__ float g_wgt[EE];
__device__ float g_x[NN * HID];
__device__ float g_Q[NN * HID];
__device__ float g_Kf[NN * HID];
__device__ float g_V[NN * NC];
__device__ float g_Ka[NN * HID];
__device__ float g_Kb[NN * HID];
__device__ float g_coef[4 * NN];
__device__ float g_tM[HID * NC];
__device__ float g_tK[HID];
__device__ float g_Xa[NN * GW];
__device__ float g_Xb[NN * GW];

// ---------------- setup kernels --------------------------------------------
__global__ void k_zero() {
    int i = blockIdx.x * blockDim.x + threadIdx.x;
    if (i < NN) { g_deg[i] = 0; g_cnt[i] = 0; }
    if (i < HID * NC) g_tM[i] = 0.f;
    if (i < HID) g_tK[i] = 0.f;
}

__global__ void k_hist(const int* __restrict__ col) {
    int e = blockIdx.x * blockDim.x + threadIdx.x;
    if (e < EE) atomicAdd(&g_deg[col[e]], 1);
}

__global__ void k_dinv() {
    int i = blockIdx.x * blockDim.x + threadIdx.x;
    if (i < NN) {
        int d = g_deg[i];
        g_dinv[i] = (d > 0) ? 1.0f / (float)d : 0.0f;
    }
}

__global__ void k_scan() {
    __shared__ int sm[1024];
    int tid = threadIdx.x;
    const int per = (NN + 1023) / 1024;  // 49
    int base = tid * per;
    int s = 0;
    for (int i = 0; i < per; i++) {
        int idx = base + i;
        if (idx < NN) s += g_deg[idx];
    }
    sm[tid] = s;
    __syncthreads();
    for (int off = 1; off < 1024; off <<= 1) {
        int v = 0;
        if (tid >= off) v = sm[tid - off];
        __syncthreads();
        if (tid >= off) sm[tid] += v;
        __syncthreads();
    }
    int run = (tid > 0) ? sm[tid - 1] : 0;
    for (int i = 0; i < per; i++) {
        int idx = base + i;
        if (idx < NN) { g_cptr[idx] = run; run += g_deg[idx]; }
    }
    if (tid == 0) g_cptr[NN] = sm[1023];
}

__global__ void k_scatter(const int* __restrict__ row, const int* __restrict__ col) {
    int e = blockIdx.x * blockDim.x + threadIdx.x;
    if (e < EE) {
        int c = col[e];
        int r = row[e];
        int pos = g_cptr[c] + atomicAdd(&g_cnt[c], 1);
        g_src[pos] = r;
        g_wgt[pos] = g_dinv[r];
    }
}

// ---------------- input GEMMs ----------------------------------------------
// x = relu(node_feat @ W_in + b_in) : [N,128]@[128,64]
__global__ void k_gemmA(const float* __restrict__ nf, const float* __restrict__ W,
                        const float* __restrict__ b) {
    __shared__ __align__(16) float Ws[NFEAT * HID];
    __shared__ __align__(16) float xs[16 * NFEAT];
    __shared__ __align__(16) float bs[HID];
    int tid = threadIdx.y * 16 + threadIdx.x;
    for (int i = tid; i < NFEAT * HID; i += 256) Ws[i] = W[i];
    if (tid < HID) bs[tid] = b[tid];
    int nb = blockIdx.x * 16;
    for (int i = tid; i < 16 * NFEAT; i += 256) {
        int n = i >> 7, f = i & 127;
        xs[i] = nf[(nb + n) * NFEAT + f];
    }
    __syncthreads();
    int node = nb + threadIdx.y;
    int oq = threadIdx.x;
    float4 acc = *(const float4*)&bs[oq * 4];
    const float* xr = &xs[threadIdx.y * NFEAT];
#pragma unroll 8
    for (int f = 0; f < NFEAT; f++) {
        float v = xr[f];
        float4 w = *(const float4*)&Ws[f * HID + oq * 4];
        acc.x += v * w.x; acc.y += v * w.y; acc.z += v * w.z; acc.w += v * w.w;
    }
    acc.x = fmaxf(acc.x, 0.f); acc.y = fmaxf(acc.y, 0.f);
    acc.z = fmaxf(acc.z, 0.f); acc.w = fmaxf(acc.w, 0.f);
    *(float4*)&g_x[node * HID + oq * 4] = acc;
}

// Q = 1+elu(x@WQ+bQ), Kf = 1+elu(x@WK+bK), V = x@WV+bV
__global__ void k_gemmB(const float* __restrict__ WQ, const float* __restrict__ bQ,
                        const float* __restrict__ WK, const float* __restrict__ bK,
                        const float* __restrict__ WV, const float* __restrict__ bV) {
    __shared__ __align__(16) float Wc[HID * 160];
    __shared__ __align__(16) float xs[8 * HID];
    __shared__ __align__(16) float bc[160];
    int tid = threadIdx.y * 40 + threadIdx.x;  // 320 threads
    for (int i = tid; i < HID * 160; i += 320) {
        int f = i / 160, o = i % 160;
        float v;
        if (o < 64) v = WQ[f * 64 + o];
        else if (o < 128) v = WK[f * 64 + (o - 64)];
        else v = WV[f * 32 + (o - 128)];
        Wc[i] = v;
    }
    if (tid < 160)
        bc[tid] = (tid < 64) ? bQ[tid] : ((tid < 128) ? bK[tid - 64] : bV[tid - 128]);
    int nb = blockIdx.x * 8;
    for (int i = tid; i < 8 * HID; i += 320) {
        int n = i >> 6, f = i & 63;
        xs[i] = g_x[(nb + n) * HID + f];
    }
    __syncthreads();
    int node = nb + threadIdx.y;
    int oq = threadIdx.x;
    float4 acc = *(const float4*)&bc[oq * 4];
    const float* xr = &xs[threadIdx.y * HID];
#pragma unroll 8
    for (int f = 0; f < HID; f++) {
        float v = xr[f];
        float4 w = *(const float4*)&Wc[f * 160 + oq * 4];
        acc.x += v * w.x; acc.y += v * w.y; acc.z += v * w.z; acc.w += v * w.w;
    }
    if (oq < 32) {
        float4 r;
        r.x = acc.x > 0.f ? 1.f + acc.x : expf(acc.x);
        r.y = acc.y > 0.f ? 1.f + acc.y : expf(acc.y);
        r.z = acc.z > 0.f ? 1.f + acc.z : expf(acc.z);
        r.w = acc.w > 0.f ? 1.f + acc.w : expf(acc.w);
        if (oq < 16) *(float4*)&g_Q[node * HID + oq * 4] = r;
        else         *(float4*)&g_Kf[node * HID + (oq - 16) * 4] = r;
    } else {
        *(float4*)&g_V[node * NC + (oq - 32) * 4] = acc;
    }
}

// ---------------- teleport reduction ---------------------------------------
__global__ void k_tele() {
    __shared__ __align__(16) float sK[8 * HID];
    __shared__ __align__(16) float sV[8 * NC];
    int tid = threadIdx.x;  // 256
    float accM[8];
#pragma unroll
    for (int j = 0; j < 8; j++) accM[j] = 0.f;
    float accK = 0.f;
    for (int nb = blockIdx.x * 8; nb < NN; nb += gridDim.x * 8) {
        __syncthreads();
        for (int i = tid; i < 8 * HID; i += 256) {
            int n = i >> 6, f = i & 63;
            int node = nb + n;
            sK[i] = (node < NN) ? g_Kf[node * HID + f] : 0.f;
        }
        for (int i = tid; i < 8 * NC; i += 256) {
            int n = i >> 5, c = i & 31;
            int node = nb + n;
            sV[i] = (node < NN) ? g_V[node * NC + c] : 0.f;
        }
        __syncthreads();
#pragma unroll
        for (int j = 0; j < 8; j++) {
            int cell = j * 256 + tid;
            int ii = cell >> 5, cc = cell & 31;
            float a = 0.f;
#pragma unroll
            for (int n = 0; n < 8; n++) a += sK[n * HID + ii] * sV[n * NC + cc];
            accM[j] += a;
        }
        if (tid < HID) {
            float a = 0.f;
#pragma unroll
            for (int n = 0; n < 8; n++) a += sK[n * HID + tid];
            accK += a;
        }
    }
#pragma unroll
    for (int j = 0; j < 8; j++) atomicAdd(&g_tM[j * 256 + tid], accM[j]);
    if (tid < HID) atomicAdd(&g_tK[tid], accK);
}

// hidden init: hopwise[0]*V + teleport * (Q@tM/n) / (Q.tK/n + CST)
__global__ void k_init(const float* __restrict__ hopwise,
                       const float* __restrict__ teleport,
                       float* __restrict__ out) {
    __shared__ __align__(16) float sM[HID * NC];
    __shared__ float sKn[HID];
    int tid = threadIdx.x;
    const float inv_n = 1.0f / (float)NN;
    for (int i = tid; i < HID * NC; i += 256) sM[i] = g_tM[i] * inv_n;
    if (tid < HID) sKn[tid] = g_tK[tid] * inv_n;
    __syncthreads();
    int w = tid >> 5, lane = tid & 31;
    int j = blockIdx.x * 8 + w;
    if (j >= NN) return;
    float q0 = g_Q[j * HID + lane];
    float q1 = g_Q[j * HID + 32 + lane];
    float th = 0.f;
#pragma unroll
    for (int i = 0; i < 32; i++) th += __shfl_sync(FULL, q0, i) * sM[i * NC + lane];
#pragma unroll
    for (int i = 0; i < 32; i++) th += __shfl_sync(FULL, q1, i) * sM[(i + 32) * NC + lane];
    float p = q0 * sKn[lane] + q1 * sKn[32 + lane];
#pragma unroll
    for (int o = 16; o > 0; o >>= 1) p += __shfl_xor_sync(FULL, p, o);
    float tc = p + CSTF;
    out[j * NC + lane] = hopwise[0] * g_V[j * NC + lane] + teleport[0] * th / tc;
}

// ---------------- Kf propagation + coef ------------------------------------
__device__ __forceinline__ const float* selK(int s) {
    return s == 0 ? g_Kf : (s == 1 ? g_Ka : g_Kb);
}
__device__ __forceinline__ float* selKw(int s) { return s == 1 ? g_Ka : g_Kb; }

__global__ void k_propK(int in_sel, int out_sel, const float* __restrict__ hopwise, int hop) {
    const float* Kin = selK(in_sel);
    float* Kout = selKw(out_sel);
    int w = threadIdx.x >> 5, lane = threadIdx.x & 31;
    int j = blockIdx.x * 8 + w;
    if (j >= NN) return;
    int r0 = g_cptr[j], r1 = g_cptr[j + 1];
    float2 acc = make_float2(0.f, 0.f);
    for (int base = r0; base < r1; base += 32) {
        int idx = base + lane;
        int s = 0; float ww = 0.f;
        if (idx < r1) { s = g_src[idx]; ww = g_wgt[idx]; }
        int m = min(32, r1 - base);
        for (int i = 0; i < m; i++) {
            int ss = __shfl_sync(FULL, s, i);
            float wv = __shfl_sync(FULL, ww, i);
            float2 kv = *(const float2*)&Kin[ss * HID + 2 * lane];
            acc.x += wv * kv.x;
            acc.y += wv * kv.y;
        }
    }
    *(float2*)&Kout[j * HID + 2 * lane] = acc;
    float2 q = *(const float2*)&g_Q[j * HID + 2 * lane];
    float p = q.x * acc.x + q.y * acc.y;
#pragma unroll
    for (int o = 16; o > 0; o >>= 1) p += __shfl_xor_sync(FULL, p, o);
    if (lane == 0) g_coef[(hop - 1) * NN + j] = hopwise[hop] / (p + CSTF);
}

// ---------------- M propagation (grouped, L2-resident) ---------------------
__global__ void k_buildX(int g) {
    int idx = blockIdx.x * blockDim.x + threadIdx.x;  // N*GW
    if (idx < NN * GW) {
        int j = idx >> 7;
        int cidx = idx & 127;
        int k = cidx >> 5, c = cidx & 31;
        g_Xa[idx] = g_Kf[j * HID + g * 4 + k] * g_V[j * NC + c];
    }
}

__global__ void k_propM(int swap, int writeX, int hop, int qoff, float* __restrict__ out) {
    const float* Xin = swap ? g_Xb : g_Xa;
    float* Xout = swap ? g_Xa : g_Xb;
    const float* coefh = g_coef + (hop - 1) * NN;
    int w = threadIdx.x >> 5, lane = threadIdx.x & 31;
    int j = blockIdx.x * 8 + w;
    if (j >= NN) return;
    int r0 = g_cptr[j], r1 = g_cptr[j + 1];
    float4 acc = make_float4(0.f, 0.f, 0.f, 0.f);
    for (int base = r0; base < r1; base += 32) {
        int idx = base + lane;
        int s = 0; float ww = 0.f;
        if (idx < r1) { s = g_src[idx]; ww = g_wgt[idx]; }
        int m = min(32, r1 - base);
        for (int i = 0; i < m; i++) {
            int ss = __shfl_sync(FULL, s, i);
            float wv = __shfl_sync(FULL, ww, i);
            float4 xv = *(const float4*)&Xin[ss * GW + 4 * lane];
            acc.x += wv * xv.x; acc.y += wv * xv.y;
            acc.z += wv * xv.z; acc.w += wv * xv.w;
        }
    }
    if (writeX) *(float4*)&Xout[j * GW + 4 * lane] = acc;
    float qv = g_Q[j * HID + qoff + (lane >> 3)];
    float4 h;
    h.x = acc.x * qv; h.y = acc.y * qv; h.z = acc.z * qv; h.w = acc.w * qv;
    h.x += __shfl_xor_sync(FULL, h.x, 8);
    h.y += __shfl_xor_sync(FULL, h.y, 8);
    h.z += __shfl_xor_sync(FULL, h.z, 8);
    h.w += __shfl_xor_sync(FULL, h.w, 8);
    h.x += __shfl_xor_sync(FULL, h.x, 16);
    h.y += __shfl_xor_sync(FULL, h.y, 16);
    h.z += __shfl_xor_sync(FULL, h.z, 16);
    h.w += __shfl_xor_sync(FULL, h.w, 16);
    if (lane < 8) {
        float cf = coefh[j];
        float4 o = *(float4*)&out[j * NC + 4 * lane];
        o.x += cf * h.x; o.y += cf * h.y;
        o.z += cf * h.z; o.w += cf * h.w;
        *(float4*)&out[j * NC + 4 * lane] = o;
    }
}

// ---------------- launch ----------------------------------------------------
extern "C" void kernel_launch(void* const* d_in, const int* in_sizes, int n_in,
                              void* d_out, int out_size) {
    const float* nf       = (const float*)d_in[0];
    const float* W_in     = (const float*)d_in[1];
    const float* b_in     = (const float*)d_in[2];
    const float* WQ       = (const float*)d_in[3];
    const float* bQ       = (const float*)d_in[4];
    const float* WK       = (const float*)d_in[5];
    const float* bK       = (const float*)d_in[6];
    const float* WV       = (const float*)d_in[7];
    const float* bV       = (const float*)d_in[8];
    const float* hopwise  = (const float*)d_in[9];
    const float* teleport = (const float*)d_in[10];
    const int*   ei       = (const int*)d_in[11];
    const int* row = ei;
    const int* col = ei + EE;
    float* out = (float*)d_out;

    k_zero<<<(NN + 255) / 256, 256>>>();
    k_hist<<<EE / 256, 256>>>(col);
    k_dinv<<<(NN + 255) / 256, 256>>>();
    k_scan<<<1, 1024>>>();
    k_scatter<<<EE / 256, 256>>>(row, col);
    k_gemmA<<<NN / 16, dim3(16, 16)>>>(nf, W_in, b_in);
    k_gemmB<<<NN / 8, dim3(40, 8)>>>(WQ, bQ, WK, bK, WV, bV);
    k_tele<<<200, 256>>>();
    k_init<<<NN / 8, 256>>>(hopwise, teleport, out);
    // Kf hops: Kf -> Ka -> Kb -> Ka -> Kb; coef per hop
    k_propK<<<NN / 8, 256>>>(0, 1, hopwise, 1);
    k_propK<<<NN / 8, 256>>>(1, 2, hopwise, 2);
    k_propK<<<NN / 8, 256>>>(2, 1, hopwise, 3);
    k_propK<<<NN / 8, 256>>>(1, 2, hopwise, 4);
    // M propagation per k-group, all 4 hops while L2-resident
    for (int g = 0; g < KG; g++) {
        k_buildX<<<(NN * GW) / 1024, 1024>>>(g);
        k_propM<<<NN / 8, 256>>>(0, 1, 1, g * 4, out);  // Xa->Xb
        k_propM<<<NN / 8, 256>>>(1, 1, 2, g * 4, out);  // Xb->Xa
        k_propM<<<NN / 8, 256>>>(0, 1, 3, g * 4, out);  // Xa->Xb
        k_propM<<<NN / 8, 256>>>(1, 0, 4, g * 4, out);  // Xb (no write)
    }
}

// round 5
// speedup vs baseline: 1.5408x; 1.5408x over previous
#include <cuda_runtime.h>
#include <cuda_fp16.h>
#include <math.h>

#define NN 50000
#define EE 1600000
#define HID 64
#define NC 32
#define NFEAT 128
#define NG 8           // k-groups (64/8)
#define GK 8           // k-cols per group
#define GWH 256        // halves per X row = GK*NC
#define CSTF 1e-5f
#define FULL 0xffffffffu

// ---------------- scratch (device globals; no allocation allowed) ----------
__device__ int    g_deg[NN];
__device__ float  g_dinv[NN];
__device__ int    g_cptr[NN + 1];
__device__ int    g_cnt[NN];
__device__ int    g_src[EE];
__device__ float  g_wgt[EE];
__device__ float  g_x[NN * HID];
__device__ float  g_Q[NN * HID];
__device__ float  g_Kf[NN * HID];
__device__ float  g_V[NN * NC];
__device__ __half g_Kh[NN * HID];
__device__ __half g_Vh[NN * NC];
__device__ float  g_Ka[NN * HID];
__device__ float  g_Kb[NN * HID];
__device__ float  g_coef[4 * NN];
__device__ float  g_tM[HID * NC];
__device__ float  g_tK[HID];
__device__ __half g_Xa[NN * GWH];
__device__ __half g_Xb[NN * GWH];

// ---------------- setup kernels --------------------------------------------
__global__ void k_zero() {
    int i = blockIdx.x * blockDim.x + threadIdx.x;
    if (i < NN) { g_deg[i] = 0; g_cnt[i] = 0; }
    if (i < HID * NC) g_tM[i] = 0.f;
    if (i < HID) g_tK[i] = 0.f;
}

__global__ void k_hist(const int* __restrict__ col) {
    int e = blockIdx.x * blockDim.x + threadIdx.x;
    if (e < EE) atomicAdd(&g_deg[col[e]], 1);
}

__global__ void k_dinv() {
    int i = blockIdx.x * blockDim.x + threadIdx.x;
    if (i < NN) {
        int d = g_deg[i];
        g_dinv[i] = (d > 0) ? 1.0f / (float)d : 0.0f;
    }
}

__global__ void k_scan() {
    __shared__ int sm[1024];
    int tid = threadIdx.x;
    const int per = (NN + 1023) / 1024;  // 49
    int base = tid * per;
    int s = 0;
    for (int i = 0; i < per; i++) {
        int idx = base + i;
        if (idx < NN) s += g_deg[idx];
    }
    sm[tid] = s;
    __syncthreads();
    for (int off = 1; off < 1024; off <<= 1) {
        int v = 0;
        if (tid >= off) v = sm[tid - off];
        __syncthreads();
        if (tid >= off) sm[tid] += v;
        __syncthreads();
    }
    int run = (tid > 0) ? sm[tid - 1] : 0;
    for (int i = 0; i < per; i++) {
        int idx = base + i;
        if (idx < NN) { g_cptr[idx] = run; run += g_deg[idx]; }
    }
    if (tid == 0) g_cptr[NN] = sm[1023];
}

__global__ void k_scatter(const int* __restrict__ row, const int* __restrict__ col) {
    int e = blockIdx.x * blockDim.x + threadIdx.x;
    if (e < EE) {
        int c = col[e];
        int r = row[e];
        int pos = g_cptr[c] + atomicAdd(&g_cnt[c], 1);
        g_src[pos] = r;
        g_wgt[pos] = g_dinv[r];
    }
}

// ---------------- input GEMMs ----------------------------------------------
__global__ void k_gemmA(const float* __restrict__ nf, const float* __restrict__ W,
                        const float* __restrict__ b) {
    __shared__ __align__(16) float Ws[NFEAT * HID];
    __shared__ __align__(16) float xs[16 * NFEAT];
    __shared__ __align__(16) float bs[HID];
    int tid = threadIdx.y * 16 + threadIdx.x;
    for (int i = tid; i < NFEAT * HID; i += 256) Ws[i] = W[i];
    if (tid < HID) bs[tid] = b[tid];
    int nb = blockIdx.x * 16;
    for (int i = tid; i < 16 * NFEAT; i += 256) {
        int n = i >> 7, f = i & 127;
        xs[i] = nf[(nb + n) * NFEAT + f];
    }
    __syncthreads();
    int node = nb + threadIdx.y;
    int oq = threadIdx.x;
    float4 acc = *(const float4*)&bs[oq * 4];
    const float* xr = &xs[threadIdx.y * NFEAT];
#pragma unroll 8
    for (int f = 0; f < NFEAT; f++) {
        float v = xr[f];
        float4 w = *(const float4*)&Ws[f * HID + oq * 4];
        acc.x += v * w.x; acc.y += v * w.y; acc.z += v * w.z; acc.w += v * w.w;
    }
    acc.x = fmaxf(acc.x, 0.f); acc.y = fmaxf(acc.y, 0.f);
    acc.z = fmaxf(acc.z, 0.f); acc.w = fmaxf(acc.w, 0.f);
    *(float4*)&g_x[node * HID + oq * 4] = acc;
}

__global__ void k_gemmB(const float* __restrict__ WQ, const float* __restrict__ bQ,
                        const float* __restrict__ WK, const float* __restrict__ bK,
                        const float* __restrict__ WV, const float* __restrict__ bV) {
    __shared__ __align__(16) float Wc[HID * 160];
    __shared__ __align__(16) float xs[8 * HID];
    __shared__ __align__(16) float bc[160];
    int tid = threadIdx.y * 40 + threadIdx.x;  // 320 threads
    for (int i = tid; i < HID * 160; i += 320) {
        int f = i / 160, o = i % 160;
        float v;
        if (o < 64) v = WQ[f * 64 + o];
        else if (o < 128) v = WK[f * 64 + (o - 64)];
        else v = WV[f * 32 + (o - 128)];
        Wc[i] = v;
    }
    if (tid < 160)
        bc[tid] = (tid < 64) ? bQ[tid] : ((tid < 128) ? bK[tid - 64] : bV[tid - 128]);
    int nb = blockIdx.x * 8;
    for (int i = tid; i < 8 * HID; i += 320) {
        int n = i >> 6, f = i & 63;
        xs[i] = g_x[(nb + n) * HID + f];
    }
    __syncthreads();
    int node = nb + threadIdx.y;
    int oq = threadIdx.x;
    float4 acc = *(const float4*)&bc[oq * 4];
    const float* xr = &xs[threadIdx.y * HID];
#pragma unroll 8
    for (int f = 0; f < HID; f++) {
        float v = xr[f];
        float4 w = *(const float4*)&Wc[f * 160 + oq * 4];
        acc.x += v * w.x; acc.y += v * w.y; acc.z += v * w.z; acc.w += v * w.w;
    }
    if (oq < 32) {
        float4 r;
        r.x = acc.x > 0.f ? 1.f + acc.x : expf(acc.x);
        r.y = acc.y > 0.f ? 1.f + acc.y : expf(acc.y);
        r.z = acc.z > 0.f ? 1.f + acc.z : expf(acc.z);
        r.w = acc.w > 0.f ? 1.f + acc.w : expf(acc.w);
        if (oq < 16) {
            *(float4*)&g_Q[node * HID + oq * 4] = r;
        } else {
            *(float4*)&g_Kf[node * HID + (oq - 16) * 4] = r;
            __half2* kh = (__half2*)&g_Kh[node * HID + (oq - 16) * 4];
            kh[0] = __floats2half2_rn(r.x, r.y);
            kh[1] = __floats2half2_rn(r.z, r.w);
        }
    } else {
        *(float4*)&g_V[node * NC + (oq - 32) * 4] = acc;
        __half2* vh = (__half2*)&g_Vh[node * NC + (oq - 32) * 4];
        vh[0] = __floats2half2_rn(acc.x, acc.y);
        vh[1] = __floats2half2_rn(acc.z, acc.w);
    }
}

// ---------------- teleport reduction ---------------------------------------
__global__ void k_tele() {
    __shared__ __align__(16) float sK[8 * HID];
    __shared__ __align__(16) float sV[8 * NC];
    int tid = threadIdx.x;  // 256
    float accM[8];
#pragma unroll
    for (int j = 0; j < 8; j++) accM[j] = 0.f;
    float accK = 0.f;
    for (int nb = blockIdx.x * 8; nb < NN; nb += gridDim.x * 8) {
        __syncthreads();
        for (int i = tid; i < 8 * HID; i += 256) {
            int n = i >> 6, f = i & 63;
            int node = nb + n;
            sK[i] = (node < NN) ? g_Kf[node * HID + f] : 0.f;
        }
        for (int i = tid; i < 8 * NC; i += 256) {
            int n = i >> 5, c = i & 31;
            int node = nb + n;
            sV[i] = (node < NN) ? g_V[node * NC + c] : 0.f;
        }
        __syncthreads();
#pragma unroll
        for (int j = 0; j < 8; j++) {
            int cell = j * 256 + tid;
            int ii = cell >> 5, cc = cell & 31;
            float a = 0.f;
#pragma unroll
            for (int n = 0; n < 8; n++) a += sK[n * HID + ii] * sV[n * NC + cc];
            accM[j] += a;
        }
        if (tid < HID) {
            float a = 0.f;
#pragma unroll
            for (int n = 0; n < 8; n++) a += sK[n * HID + tid];
            accK += a;
        }
    }
#pragma unroll
    for (int j = 0; j < 8; j++) atomicAdd(&g_tM[j * 256 + tid], accM[j]);
    if (tid < HID) atomicAdd(&g_tK[tid], accK);
}

// hidden init: hopwise[0]*V + teleport * (Q@tM/n) / (Q.tK/n + CST)
__global__ void k_init(const float* __restrict__ hopwise,
                       const float* __restrict__ teleport,
                       float* __restrict__ out) {
    __shared__ __align__(16) float sM[HID * NC];
    __shared__ float sKn[HID];
    int tid = threadIdx.x;
    const float inv_n = 1.0f / (float)NN;
    for (int i = tid; i < HID * NC; i += 256) sM[i] = g_tM[i] * inv_n;
    if (tid < HID) sKn[tid] = g_tK[tid] * inv_n;
    __syncthreads();
    int w = tid >> 5, lane = tid & 31;
    int j = blockIdx.x * 8 + w;
    if (j >= NN) return;
    float q0 = g_Q[j * HID + lane];
    float q1 = g_Q[j * HID + 32 + lane];
    float th = 0.f;
#pragma unroll
    for (int i = 0; i < 32; i++) th += __shfl_sync(FULL, q0, i) * sM[i * NC + lane];
#pragma unroll
    for (int i = 0; i < 32; i++) th += __shfl_sync(FULL, q1, i) * sM[(i + 32) * NC + lane];
    float p = q0 * sKn[lane] + q1 * sKn[32 + lane];
#pragma unroll
    for (int o = 16; o > 0; o >>= 1) p += __shfl_xor_sync(FULL, p, o);
    float tc = p + CSTF;
    out[j * NC + lane] = hopwise[0] * g_V[j * NC + lane] + teleport[0] * th / tc;
}

// ---------------- Kf propagation + coef ------------------------------------
__device__ __forceinline__ const float* selK(int s) {
    return s == 0 ? g_Kf : (s == 1 ? g_Ka : g_Kb);
}
__device__ __forceinline__ float* selKw(int s) { return s == 1 ? g_Ka : g_Kb; }

__global__ void k_propK(int in_sel, int out_sel, const float* __restrict__ hopwise, int hop) {
    const float* Kin = selK(in_sel);
    float* Kout = selKw(out_sel);
    int w = threadIdx.x >> 5, lane = threadIdx.x & 31;
    int j = blockIdx.x * 8 + w;
    if (j >= NN) return;
    int r0 = g_cptr[j], r1 = g_cptr[j + 1];
    float2 acc = make_float2(0.f, 0.f);
    for (int base = r0; base < r1; base += 32) {
        int idx = base + lane;
        int s = 0; float ww = 0.f;
        if (idx < r1) { s = g_src[idx]; ww = g_wgt[idx]; }
        int m = min(32, r1 - base);
        for (int i = 0; i < m; i++) {
            int ss = __shfl_sync(FULL, s, i);
            float wv = __shfl_sync(FULL, ww, i);
            float2 kv = *(const float2*)&Kin[ss * HID + 2 * lane];
            acc.x += wv * kv.x;
            acc.y += wv * kv.y;
        }
    }
    *(float2*)&Kout[j * HID + 2 * lane] = acc;
    float2 q = *(const float2*)&g_Q[j * HID + 2 * lane];
    float p = q.x * acc.x + q.y * acc.y;
#pragma unroll
    for (int o = 16; o > 0; o >>= 1) p += __shfl_xor_sync(FULL, p, o);
    if (lane == 0) g_coef[(hop - 1) * NN + j] = hopwise[hop] / (p + CSTF);
}

// ---------------- shared epilogue: Q-contract + out accumulate --------------
// lane l holds 8 c-values for k = qoff + (l>>2), c = (l&3)*8 .. +8
__device__ __forceinline__ void epilogue(float f[8], int j, int lane, int qoff,
                                         const float* coefh, float* out) {
    float qv = g_Q[j * HID + qoff + (lane >> 2)];
#pragma unroll
    for (int m = 0; m < 8; m++) f[m] *= qv;
#pragma unroll
    for (int mask = 4; mask <= 16; mask <<= 1) {
#pragma unroll
        for (int m = 0; m < 8; m++) f[m] += __shfl_xor_sync(FULL, f[m], mask);
    }
    if (lane < 4) {
        float cf = coefh[j];
        float4* o = (float4*)&out[j * NC + lane * 8];
        float4 o0 = o[0], o1 = o[1];
        o0.x += cf * f[0]; o0.y += cf * f[1]; o0.z += cf * f[2]; o0.w += cf * f[3];
        o1.x += cf * f[4]; o1.y += cf * f[5]; o1.z += cf * f[6]; o1.w += cf * f[7];
        o[0] = o0; o[1] = o1;
    }
}

// ---------------- hop 1: rank-1 fused gather (Kf ⊗ V), writes X1 -> Xb ------
__global__ void k_prop1(int qoff, float* __restrict__ out) {
    int w = threadIdx.x >> 5, lane = threadIdx.x & 31;
    int j = blockIdx.x * 8 + w;
    if (j >= NN) return;
    int r0 = g_cptr[j], r1 = g_cptr[j + 1];
    int kk = qoff + (lane >> 2);
    int c0 = (lane & 3) * 8;
    float f[8];
#pragma unroll
    for (int m = 0; m < 8; m++) f[m] = 0.f;
    for (int base = r0; base < r1; base += 32) {
        int idx = base + lane;
        int s = 0; float ww = 0.f;
        if (idx < r1) { s = g_src[idx]; ww = g_wgt[idx]; }
        int mm = min(32, r1 - base);
        for (int i = 0; i < mm; i++) {
            int ss = __shfl_sync(FULL, s, i);
            float wv = __shfl_sync(FULL, ww, i);
            float wk = wv * __half2float(g_Kh[ss * HID + kk]);
            uint4 vv = *(const uint4*)&g_Vh[ss * NC + c0];
            float2 p0 = __half22float2(*(__half2*)&vv.x);
            float2 p1 = __half22float2(*(__half2*)&vv.y);
            float2 p2 = __half22float2(*(__half2*)&vv.z);
            float2 p3 = __half22float2(*(__half2*)&vv.w);
            f[0] += wk * p0.x; f[1] += wk * p0.y;
            f[2] += wk * p1.x; f[3] += wk * p1.y;
            f[4] += wk * p2.x; f[5] += wk * p2.y;
            f[6] += wk * p3.x; f[7] += wk * p3.y;
        }
    }
    // store X1 (fp16) at halves [j*GWH + lane*8, +8)
    uint4 st;
    ((__half2*)&st)[0] = __floats2half2_rn(f[0], f[1]);
    ((__half2*)&st)[1] = __floats2half2_rn(f[2], f[3]);
    ((__half2*)&st)[2] = __floats2half2_rn(f[4], f[5]);
    ((__half2*)&st)[3] = __floats2half2_rn(f[6], f[7]);
    *(uint4*)&g_Xb[j * GWH + lane * 8] = st;
    epilogue(f, j, lane, qoff, g_coef, out);
}

// ---------------- hops 2..4: fp16 X gather ---------------------------------
__global__ void k_propM(int swap, int writeX, int hop, int qoff, float* __restrict__ out) {
    const __half* Xin = swap ? g_Xb : g_Xa;
    __half* Xout = swap ? g_Xa : g_Xb;
    const float* coefh = g_coef + (hop - 1) * NN;
    int w = threadIdx.x >> 5, lane = threadIdx.x & 31;
    int j = blockIdx.x * 8 + w;
    if (j >= NN) return;
    int r0 = g_cptr[j], r1 = g_cptr[j + 1];
    float f[8];
#pragma unroll
    for (int m = 0; m < 8; m++) f[m] = 0.f;
    for (int base = r0; base < r1; base += 32) {
        int idx = base + lane;
        int s = 0; float ww = 0.f;
        if (idx < r1) { s = g_src[idx]; ww = g_wgt[idx]; }
        int mm = min(32, r1 - base);
        for (int i = 0; i < mm; i++) {
            int ss = __shfl_sync(FULL, s, i);
            float wv = __shfl_sync(FULL, ww, i);
            uint4 xv = *(const uint4*)&Xin[ss * GWH + lane * 8];
            float2 p0 = __half22float2(*(__half2*)&xv.x);
            float2 p1 = __half22float2(*(__half2*)&xv.y);
            float2 p2 = __half22float2(*(__half2*)&xv.z);
            float2 p3 = __half22float2(*(__half2*)&xv.w);
            f[0] += wv * p0.x; f[1] += wv * p0.y;
            f[2] += wv * p1.x; f[3] += wv * p1.y;
            f[4] += wv * p2.x; f[5] += wv * p2.y;
            f[6] += wv * p3.x; f[7] += wv * p3.y;
        }
    }
    if (writeX) {
        uint4 st;
        ((__half2*)&st)[0] = __floats2half2_rn(f[0], f[1]);
        ((__half2*)&st)[1] = __floats2half2_rn(f[2], f[3]);
        ((__half2*)&st)[2] = __floats2half2_rn(f[4], f[5]);
        ((__half2*)&st)[3] = __floats2half2_rn(f[6], f[7]);
        *(uint4*)&Xout[j * GWH + lane * 8] = st;
    }
    epilogue(f, j, lane, qoff, coefh, out);
}

// ---------------- launch ----------------------------------------------------
extern "C" void kernel_launch(void* const* d_in, const int* in_sizes, int n_in,
                              void* d_out, int out_size) {
    const float* nf       = (const float*)d_in[0];
    const float* W_in     = (const float*)d_in[1];
    const float* b_in     = (const float*)d_in[2];
    const float* WQ       = (const float*)d_in[3];
    const float* bQ       = (const float*)d_in[4];
    const float* WK       = (const float*)d_in[5];
    const float* bK       = (const float*)d_in[6];
    const float* WV       = (const float*)d_in[7];
    const float* bV       = (const float*)d_in[8];
    const float* hopwise  = (const float*)d_in[9];
    const float* teleport = (const float*)d_in[10];
    const int*   ei       = (const int*)d_in[11];
    const int* row = ei;
    const int* col = ei + EE;
    float* out = (float*)d_out;

    k_zero<<<(NN + 255) / 256, 256>>>();
    k_hist<<<EE / 256, 256>>>(col);
    k_dinv<<<(NN + 255) / 256, 256>>>();
    k_scan<<<1, 1024>>>();
    k_scatter<<<EE / 256, 256>>>(row, col);
    k_gemmA<<<NN / 16, dim3(16, 16)>>>(nf, W_in, b_in);
    k_gemmB<<<NN / 8, dim3(40, 8)>>>(WQ, bQ, WK, bK, WV, bV);
    k_tele<<<200, 256>>>();
    k_init<<<NN / 8, 256>>>(hopwise, teleport, out);
    // Kf hops: Kf -> Ka -> Kb -> Ka -> Kb; coef per hop
    k_propK<<<NN / 8, 256>>>(0, 1, hopwise, 1);
    k_propK<<<NN / 8, 256>>>(1, 2, hopwise, 2);
    k_propK<<<NN / 8, 256>>>(2, 1, hopwise, 3);
    k_propK<<<NN / 8, 256>>>(1, 2, hopwise, 4);
    // M propagation per 8-wide k-group; hop1 fused rank-1, hops 2-4 fp16 X
    for (int g = 0; g < NG; g++) {
        k_prop1<<<NN / 8, 256>>>(g * GK, out);          // -> Xb (hop 1)
        k_propM<<<NN / 8, 256>>>(1, 1, 2, g * GK, out); // Xb -> Xa
        k_propM<<<NN / 8, 256>>>(0, 1, 3, g * GK, out); // Xa -> Xb
        k_propM<<<NN / 8, 256>>>(1, 0, 4, g * GK, out); // Xb (no write)
    }
}

// round 6
// speedup vs baseline: 1.8776x; 1.2186x over previous
#include <cuda_runtime.h>
#include <cuda_fp16.h>
#include <math.h>

#define NN 50000
#define EE 1600000
#define HID 64
#define NC 32
#define NFEAT 128
#define NG 8           // k-groups (64/8)
#define GK 8           // k-cols per group
#define GWH 256        // halves per X row = GK*NC
#define CSTF 1e-5f
#define FULL 0xffffffffu
#define NBLK ((NN + 255) / 256)   // 196 scan blocks

// ---------------- scratch (device globals; no allocation allowed) ----------
__device__ int    g_deg[NN];
__device__ float  g_dinv[NN];
__device__ int    g_cptr[NN + 1];
__device__ int    g_cnt[NN];
__device__ float2 g_swp[EE];      // packed (src-as-float-bits, wgt)
__device__ int    g_bsum[NBLK];
__device__ int    g_boff[NBLK];
__device__ float  g_x[NN * HID];
__device__ float  g_Q[NN * HID];
__device__ float  g_Kf[NN * HID];
__device__ float  g_V[NN * NC];
__device__ __half g_Kh[NN * HID];
__device__ __half g_Vh[NN * NC];
__device__ float  g_Ka[NN * HID];
__device__ float  g_Kb[NN * HID];
__device__ float  g_coef[4 * NN];
__device__ float  g_tM[HID * NC];
__device__ float  g_tK[HID];
__device__ __half g_Xa[NN * GWH];
__device__ __half g_Xb[NN * GWH];

// ---------------- setup kernels --------------------------------------------
__global__ void k_zero() {
    int i = blockIdx.x * blockDim.x + threadIdx.x;
    if (i < NN) { g_deg[i] = 0; g_cnt[i] = 0; }
    if (i < HID * NC) g_tM[i] = 0.f;
    if (i < HID) g_tK[i] = 0.f;
}

__global__ void k_hist(const int* __restrict__ col) {
    int e = blockIdx.x * blockDim.x + threadIdx.x;
    if (e < EE) atomicAdd(&g_deg[col[e]], 1);
}

__global__ void k_dinv() {
    int i = blockIdx.x * blockDim.x + threadIdx.x;
    if (i < NN) {
        int d = g_deg[i];
        g_dinv[i] = (d > 0) ? 1.0f / (float)d : 0.0f;
    }
}

// hierarchical scan: block sums -> 1-block exclusive scan -> cptr write
__global__ void k_blksum() {
    __shared__ int sm[256];
    int b = blockIdx.x, t = threadIdx.x;
    int i = b * 256 + t;
    sm[t] = (i < NN) ? g_deg[i] : 0;
    __syncthreads();
    for (int o = 128; o > 0; o >>= 1) {
        if (t < o) sm[t] += sm[t + o];
        __syncthreads();
    }
    if (t == 0) g_bsum[b] = sm[0];
}

__global__ void k_scanblk() {
    __shared__ int sm[256];
    int t = threadIdx.x;
    int v = (t < NBLK) ? g_bsum[t] : 0;
    sm[t] = v;
    __syncthreads();
    for (int o = 1; o < 256; o <<= 1) {
        int u = 0;
        if (t >= o) u = sm[t - o];
        __syncthreads();
        sm[t] += u;
        __syncthreads();
    }
    if (t < NBLK) g_boff[t] = sm[t] - v;   // exclusive
}

__global__ void k_cptr() {
    __shared__ int sm[256];
    int b = blockIdx.x, t = threadIdx.x;
    int i = b * 256 + t;
    int v = (i < NN) ? g_deg[i] : 0;
    sm[t] = v;
    __syncthreads();
    for (int o = 1; o < 256; o <<= 1) {
        int u = 0;
        if (t >= o) u = sm[t - o];
        __syncthreads();
        sm[t] += u;
        __syncthreads();
    }
    int incl = sm[t];
    if (i < NN) g_cptr[i] = g_boff[b] + incl - v;
    if (i == NN - 1) g_cptr[NN] = g_boff[b] + incl;
}

__global__ void k_scatter(const int* __restrict__ row, const int* __restrict__ col) {
    int e = blockIdx.x * blockDim.x + threadIdx.x;
    if (e < EE) {
        int c = col[e];
        int r = row[e];
        int pos = g_cptr[c] + atomicAdd(&g_cnt[c], 1);
        g_swp[pos] = make_float2(__int_as_float(r), g_dinv[r]);
    }
}

// ---------------- input GEMMs ----------------------------------------------
__global__ void k_gemmA(const float* __restrict__ nf, const float* __restrict__ W,
                        const float* __restrict__ b) {
    __shared__ __align__(16) float Ws[NFEAT * HID];
    __shared__ __align__(16) float xs[16 * NFEAT];
    __shared__ __align__(16) float bs[HID];
    int tid = threadIdx.y * 16 + threadIdx.x;
    for (int i = tid; i < NFEAT * HID; i += 256) Ws[i] = W[i];
    if (tid < HID) bs[tid] = b[tid];
    int nb = blockIdx.x * 16;
    for (int i = tid; i < 16 * NFEAT; i += 256) {
        int n = i >> 7, f = i & 127;
        xs[i] = nf[(nb + n) * NFEAT + f];
    }
    __syncthreads();
    int node = nb + threadIdx.y;
    int oq = threadIdx.x;
    float4 acc = *(const float4*)&bs[oq * 4];
    const float* xr = &xs[threadIdx.y * NFEAT];
#pragma unroll 8
    for (int f = 0; f < NFEAT; f++) {
        float v = xr[f];
        float4 w = *(const float4*)&Ws[f * HID + oq * 4];
        acc.x += v * w.x; acc.y += v * w.y; acc.z += v * w.z; acc.w += v * w.w;
    }
    acc.x = fmaxf(acc.x, 0.f); acc.y = fmaxf(acc.y, 0.f);
    acc.z = fmaxf(acc.z, 0.f); acc.w = fmaxf(acc.w, 0.f);
    *(float4*)&g_x[node * HID + oq * 4] = acc;
}

__global__ void k_gemmB(const float* __restrict__ WQ, const float* __restrict__ bQ,
                        const float* __restrict__ WK, const float* __restrict__ bK,
                        const float* __restrict__ WV, const float* __restrict__ bV) {
    __shared__ __align__(16) float Wc[HID * 160];
    __shared__ __align__(16) float xs[8 * HID];
    __shared__ __align__(16) float bc[160];
    int tid = threadIdx.y * 40 + threadIdx.x;  // 320 threads
    for (int i = tid; i < HID * 160; i += 320) {
        int f = i / 160, o = i % 160;
        float v;
        if (o < 64) v = WQ[f * 64 + o];
        else if (o < 128) v = WK[f * 64 + (o - 64)];
        else v = WV[f * 32 + (o - 128)];
        Wc[i] = v;
    }
    if (tid < 160)
        bc[tid] = (tid < 64) ? bQ[tid] : ((tid < 128) ? bK[tid - 64] : bV[tid - 128]);
    int nb = blockIdx.x * 8;
    for (int i = tid; i < 8 * HID; i += 320) {
        int n = i >> 6, f = i & 63;
        xs[i] = g_x[(nb + n) * HID + f];
    }
    __syncthreads();
    int node = nb + threadIdx.y;
    int oq = threadIdx.x;
    float4 acc = *(const float4*)&bc[oq * 4];
    const float* xr = &xs[threadIdx.y * HID];
#pragma unroll 8
    for (int f = 0; f < HID; f++) {
        float v = xr[f];
        float4 w = *(const float4*)&Wc[f * 160 + oq * 4];
        acc.x += v * w.x; acc.y += v * w.y; acc.z += v * w.z; acc.w += v * w.w;
    }
    if (oq < 32) {
        float4 r;
        r.x = acc.x > 0.f ? 1.f + acc.x : expf(acc.x);
        r.y = acc.y > 0.f ? 1.f + acc.y : expf(acc.y);
        r.z = acc.z > 0.f ? 1.f + acc.z : expf(acc.z);
        r.w = acc.w > 0.f ? 1.f + acc.w : expf(acc.w);
        if (oq < 16) {
            *(float4*)&g_Q[node * HID + oq * 4] = r;
        } else {
            *(float4*)&g_Kf[node * HID + (oq - 16) * 4] = r;
            __half2* kh = (__half2*)&g_Kh[node * HID + (oq - 16) * 4];
            kh[0] = __floats2half2_rn(r.x, r.y);
            kh[1] = __floats2half2_rn(r.z, r.w);
        }
    } else {
        *(float4*)&g_V[node * NC + (oq - 32) * 4] = acc;
        __half2* vh = (__half2*)&g_Vh[node * NC + (oq - 32) * 4];
        vh[0] = __floats2half2_rn(acc.x, acc.y);
        vh[1] = __floats2half2_rn(acc.z, acc.w);
    }
}

// ---------------- teleport reduction ---------------------------------------
__global__ void k_tele() {
    __shared__ __align__(16) float sK[8 * HID];
    __shared__ __align__(16) float sV[8 * NC];
    int tid = threadIdx.x;  // 256
    float accM[8];
#pragma unroll
    for (int j = 0; j < 8; j++) accM[j] = 0.f;
    float accK = 0.f;
    for (int nb = blockIdx.x * 8; nb < NN; nb += gridDim.x * 8) {
        __syncthreads();
        for (int i = tid; i < 8 * HID; i += 256) {
            int n = i >> 6, f = i & 63;
            int node = nb + n;
            sK[i] = (node < NN) ? g_Kf[node * HID + f] : 0.f;
        }
        for (int i = tid; i < 8 * NC; i += 256) {
            int n = i >> 5, c = i & 31;
            int node = nb + n;
            sV[i] = (node < NN) ? g_V[node * NC + c] : 0.f;
        }
        __syncthreads();
#pragma unroll
        for (int j = 0; j < 8; j++) {
            int cell = j * 256 + tid;
            int ii = cell >> 5, cc = cell & 31;
            float a = 0.f;
#pragma unroll
            for (int n = 0; n < 8; n++) a += sK[n * HID + ii] * sV[n * NC + cc];
            accM[j] += a;
        }
        if (tid < HID) {
            float a = 0.f;
#pragma unroll
            for (int n = 0; n < 8; n++) a += sK[n * HID + tid];
            accK += a;
        }
    }
#pragma unroll
    for (int j = 0; j < 8; j++) atomicAdd(&g_tM[j * 256 + tid], accM[j]);
    if (tid < HID) atomicAdd(&g_tK[tid], accK);
}

// hidden init: hopwise[0]*V + teleport * (Q@tM/n) / (Q.tK/n + CST)
__global__ void k_init(const float* __restrict__ hopwise,
                       const float* __restrict__ teleport,
                       float* __restrict__ out) {
    __shared__ __align__(16) float sM[HID * NC];
    __shared__ float sKn[HID];
    int tid = threadIdx.x;
    const float inv_n = 1.0f / (float)NN;
    for (int i = tid; i < HID * NC; i += 256) sM[i] = g_tM[i] * inv_n;
    if (tid < HID) sKn[tid] = g_tK[tid] * inv_n;
    __syncthreads();
    int w = tid >> 5, lane = tid & 31;
    int j = blockIdx.x * 8 + w;
    if (j >= NN) return;
    float q0 = g_Q[j * HID + lane];
    float q1 = g_Q[j * HID + 32 + lane];
    float th = 0.f;
#pragma unroll
    for (int i = 0; i < 32; i++) th += __shfl_sync(FULL, q0, i) * sM[i * NC + lane];
#pragma unroll
    for (int i = 0; i < 32; i++) th += __shfl_sync(FULL, q1, i) * sM[(i + 32) * NC + lane];
    float p = q0 * sKn[lane] + q1 * sKn[32 + lane];
#pragma unroll
    for (int o = 16; o > 0; o >>= 1) p += __shfl_xor_sync(FULL, p, o);
    float tc = p + CSTF;
    out[j * NC + lane] = hopwise[0] * g_V[j * NC + lane] + teleport[0] * th / tc;
}

// ---------------- Kf propagation + coef ------------------------------------
__device__ __forceinline__ const float* selK(int s) {
    return s == 0 ? g_Kf : (s == 1 ? g_Ka : g_Kb);
}
__device__ __forceinline__ float* selKw(int s) { return s == 1 ? g_Ka : g_Kb; }

__global__ void k_propK(int in_sel, int out_sel, const float* __restrict__ hopwise, int hop) {
    const float* Kin = selK(in_sel);
    float* Kout = selKw(out_sel);
    int w = threadIdx.x >> 5, lane = threadIdx.x & 31;
    int j = blockIdx.x * 8 + w;
    if (j >= NN) return;
    int r0 = g_cptr[j], r1 = g_cptr[j + 1];
    float2 acc = make_float2(0.f, 0.f);
    int off = 2 * lane;
    for (int base = r0; base < r1; base += 32) {
        int idx = base + lane;
        int s = 0; float ww = 0.f;
        if (idx < r1) {
            float2 sw = g_swp[idx];
            s = __float_as_int(sw.x); ww = sw.y;
        }
        int mm = min(32, r1 - base);
        int mmr = (mm + 3) & ~3;
        for (int i = 0; i < mmr; i += 4) {
            int s0 = __shfl_sync(FULL, s, i);
            int s1 = __shfl_sync(FULL, s, i + 1);
            int s2 = __shfl_sync(FULL, s, i + 2);
            int s3 = __shfl_sync(FULL, s, i + 3);
            float w0 = __shfl_sync(FULL, ww, i);
            float w1 = __shfl_sync(FULL, ww, i + 1);
            float w2 = __shfl_sync(FULL, ww, i + 2);
            float w3 = __shfl_sync(FULL, ww, i + 3);
            float2 k0 = *(const float2*)&Kin[s0 * HID + off];
            float2 k1 = *(const float2*)&Kin[s1 * HID + off];
            float2 k2 = *(const float2*)&Kin[s2 * HID + off];
            float2 k3 = *(const float2*)&Kin[s3 * HID + off];
            acc.x += w0 * k0.x; acc.y += w0 * k0.y;
            acc.x += w1 * k1.x; acc.y += w1 * k1.y;
            acc.x += w2 * k2.x; acc.y += w2 * k2.y;
            acc.x += w3 * k3.x; acc.y += w3 * k3.y;
        }
    }
    *(float2*)&Kout[j * HID + off] = acc;
    float2 q = *(const float2*)&g_Q[j * HID + off];
    float p = q.x * acc.x + q.y * acc.y;
#pragma unroll
    for (int o = 16; o > 0; o >>= 1) p += __shfl_xor_sync(FULL, p, o);
    if (lane == 0) g_coef[(hop - 1) * NN + j] = hopwise[hop] / (p + CSTF);
}

// ---------------- shared epilogue: Q-contract + out accumulate --------------
__device__ __forceinline__ void epilogue(float f[8], int j, int lane, int qoff,
                                         const float* coefh, float* out) {
    float qv = g_Q[j * HID + qoff + (lane >> 2)];
#pragma unroll
    for (int m = 0; m < 8; m++) f[m] *= qv;
#pragma unroll
    for (int mask = 4; mask <= 16; mask <<= 1) {
#pragma unroll
        for (int m = 0; m < 8; m++) f[m] += __shfl_xor_sync(FULL, f[m], mask);
    }
    if (lane < 4) {
        float cf = coefh[j];
        float4* o = (float4*)&out[j * NC + lane * 8];
        float4 o0 = o[0], o1 = o[1];
        o0.x += cf * f[0]; o0.y += cf * f[1]; o0.z += cf * f[2]; o0.w += cf * f[3];
        o1.x += cf * f[4]; o1.y += cf * f[5]; o1.z += cf * f[6]; o1.w += cf * f[7];
        o[0] = o0; o[1] = o1;
    }
}

__device__ __forceinline__ void acc8(float f[8], uint4 xv, float wv) {
    float2 p0 = __half22float2(*(__half2*)&xv.x);
    float2 p1 = __half22float2(*(__half2*)&xv.y);
    float2 p2 = __half22float2(*(__half2*)&xv.z);
    float2 p3 = __half22float2(*(__half2*)&xv.w);
    f[0] += wv * p0.x; f[1] += wv * p0.y;
    f[2] += wv * p1.x; f[3] += wv * p1.y;
    f[4] += wv * p2.x; f[5] += wv * p2.y;
    f[6] += wv * p3.x; f[7] += wv * p3.y;
}

// ---------------- hop 1: rank-1 fused gather (Kf ⊗ V), writes X1 -> Xb ------
__global__ void k_prop1(int qoff, float* __restrict__ out) {
    int w = threadIdx.x >> 5, lane = threadIdx.x & 31;
    int j = blockIdx.x * 8 + w;
    if (j >= NN) return;
    int r0 = g_cptr[j], r1 = g_cptr[j + 1];
    int kk = qoff + (lane >> 2);
    int c0 = (lane & 3) * 8;
    float f[8];
#pragma unroll
    for (int m = 0; m < 8; m++) f[m] = 0.f;
    for (int base = r0; base < r1; base += 32) {
        int idx = base + lane;
        int s = 0; float ww = 0.f;
        if (idx < r1) {
            float2 sw = g_swp[idx];
            s = __float_as_int(sw.x); ww = sw.y;
        }
        int mm = min(32, r1 - base);
        int mmr = (mm + 3) & ~3;
        for (int i = 0; i < mmr; i += 4) {
            int s0 = __shfl_sync(FULL, s, i);
            int s1 = __shfl_sync(FULL, s, i + 1);
            int s2 = __shfl_sync(FULL, s, i + 2);
            int s3 = __shfl_sync(FULL, s, i + 3);
            float w0 = __shfl_sync(FULL, ww, i);
            float w1 = __shfl_sync(FULL, ww, i + 1);
            float w2 = __shfl_sync(FULL, ww, i + 2);
            float w3 = __shfl_sync(FULL, ww, i + 3);
            uint4 v0 = *(const uint4*)&g_Vh[s0 * NC + c0];
            uint4 v1 = *(const uint4*)&g_Vh[s1 * NC + c0];
            uint4 v2 = *(const uint4*)&g_Vh[s2 * NC + c0];
            uint4 v3 = *(const uint4*)&g_Vh[s3 * NC + c0];
            float k0 = w0 * __half2float(g_Kh[s0 * HID + kk]);
            float k1 = w1 * __half2float(g_Kh[s1 * HID + kk]);
            float k2 = w2 * __half2float(g_Kh[s2 * HID + kk]);
            float k3 = w3 * __half2float(g_Kh[s3 * HID + kk]);
            acc8(f, v0, k0);
            acc8(f, v1, k1);
            acc8(f, v2, k2);
            acc8(f, v3, k3);
        }
    }
    uint4 st;
    ((__half2*)&st)[0] = __floats2half2_rn(f[0], f[1]);
    ((__half2*)&st)[1] = __floats2half2_rn(f[2], f[3]);
    ((__half2*)&st)[2] = __floats2half2_rn(f[4], f[5]);
    ((__half2*)&st)[3] = __floats2half2_rn(f[6], f[7]);
    *(uint4*)&g_Xb[j * GWH + lane * 8] = st;
    epilogue(f, j, lane, qoff, g_coef, out);
}

// ---------------- hops 2..4: fp16 X gather, MLP=4 --------------------------
__global__ void k_propM(int swap, int writeX, int hop, int qoff, float* __restrict__ out) {
    const __half* Xin = swap ? g_Xb : g_Xa;
    __half* Xout = swap ? g_Xa : g_Xb;
    const float* coefh = g_coef + (hop - 1) * NN;
    int w = threadIdx.x >> 5, lane = threadIdx.x & 31;
    int j = blockIdx.x * 8 + w;
    if (j >= NN) return;
    int r0 = g_cptr[j], r1 = g_cptr[j + 1];
    int off = lane * 8;
    float f[8];
#pragma unroll
    for (int m = 0; m < 8; m++) f[m] = 0.f;
    for (int base = r0; base < r1; base += 32) {
        int idx = base + lane;
        int s = 0; float ww = 0.f;
        if (idx < r1) {
            float2 sw = g_swp[idx];
            s = __float_as_int(sw.x); ww = sw.y;
        }
        int mm = min(32, r1 - base);
        int mmr = (mm + 3) & ~3;
        for (int i = 0; i < mmr; i += 4) {
            int s0 = __shfl_sync(FULL, s, i);
            int s1 = __shfl_sync(FULL, s, i + 1);
            int s2 = __shfl_sync(FULL, s, i + 2);
            int s3 = __shfl_sync(FULL, s, i + 3);
            float w0 = __shfl_sync(FULL, ww, i);
            float w1 = __shfl_sync(FULL, ww, i + 1);
            float w2 = __shfl_sync(FULL, ww, i + 2);
            float w3 = __shfl_sync(FULL, ww, i + 3);
            uint4 x0 = *(const uint4*)&Xin[s0 * GWH + off];
            uint4 x1 = *(const uint4*)&Xin[s1 * GWH + off];
            uint4 x2 = *(const uint4*)&Xin[s2 * GWH + off];
            uint4 x3 = *(const uint4*)&Xin[s3 * GWH + off];
            acc8(f, x0, w0);
            acc8(f, x1, w1);
            acc8(f, x2, w2);
            acc8(f, x3, w3);
        }
    }
    if (writeX) {
        uint4 st;
        ((__half2*)&st)[0] = __floats2half2_rn(f[0], f[1]);
        ((__half2*)&st)[1] = __floats2half2_rn(f[2], f[3]);
        ((__half2*)&st)[2] = __floats2half2_rn(f[4], f[5]);
        ((__half2*)&st)[3] = __floats2half2_rn(f[6], f[7]);
        *(uint4*)&Xout[j * GWH + off] = st;
    }
    epilogue(f, j, lane, qoff, coefh, out);
}

// ---------------- launch ----------------------------------------------------
extern "C" void kernel_launch(void* const* d_in, const int* in_sizes, int n_in,
                              void* d_out, int out_size) {
    const float* nf       = (const float*)d_in[0];
    const float* W_in     = (const float*)d_in[1];
    const float* b_in     = (const float*)d_in[2];
    const float* WQ       = (const float*)d_in[3];
    const float* bQ       = (const float*)d_in[4];
    const float* WK       = (const float*)d_in[5];
    const float* bK       = (const float*)d_in[6];
    const float* WV       = (const float*)d_in[7];
    const float* bV       = (const float*)d_in[8];
    const float* hopwise  = (const float*)d_in[9];
    const float* teleport = (const float*)d_in[10];
    const int*   ei       = (const int*)d_in[11];
    const int* row = ei;
    const int* col = ei + EE;
    float* out = (float*)d_out;

    k_zero<<<(NN + 255) / 256, 256>>>();
    k_hist<<<EE / 256, 256>>>(col);
    k_dinv<<<(NN + 255) / 256, 256>>>();
    k_blksum<<<NBLK, 256>>>();
    k_scanblk<<<1, 256>>>();
    k_cptr<<<NBLK, 256>>>();
    k_scatter<<<EE / 256, 256>>>(row, col);
    k_gemmA<<<NN / 16, dim3(16, 16)>>>(nf, W_in, b_in);
    k_gemmB<<<NN / 8, dim3(40, 8)>>>(WQ, bQ, WK, bK, WV, bV);
    k_tele<<<200, 256>>>();
    k_init<<<NN / 8, 256>>>(hopwise, teleport, out);
    // Kf hops: Kf -> Ka -> Kb -> Ka -> Kb; coef per hop
    k_propK<<<NN / 8, 256>>>(0, 1, hopwise, 1);
    k_propK<<<NN / 8, 256>>>(1, 2, hopwise, 2);
    k_propK<<<NN / 8, 256>>>(2, 1, hopwise, 3);
    k_propK<<<NN / 8, 256>>>(1, 2, hopwise, 4);
    // M propagation per 8-wide k-group; hop1 fused rank-1, hops 2-4 fp16 X
    for (int g = 0; g < NG; g++) {
        k_prop1<<<NN / 8, 256>>>(g * GK, out);          // -> Xb (hop 1)
        k_propM<<<NN / 8, 256>>>(1, 1, 2, g * GK, out); // Xb -> Xa
        k_propM<<<NN / 8, 256>>>(0, 1, 3, g * GK, out); // Xa -> Xb
        k_propM<<<NN / 8, 256>>>(1, 0, 4, g * GK, out); // Xb (no write)
    }
}